// round 14
// baseline (speedup 1.0000x reference)
#include <cuda_runtime.h>
#include <cuda_bf16.h>
#include <cuda_fp16.h>
#include <stdint.h>

#define STRB 144              // smem tile row stride, bytes
#define CEXP 0.06375846855f   // (1/sqrt(512)) * log2(e)
#define OSTR 68               // epilogue O-buf row stride (f32)
#define WSTR 88               // pos window row stride (halves)
#define PSTR 1152             // gPOS row stride (halves): 64 pad + 1024 + 64 pad

// main kernel smem
#define T_QH 0
#define T_QL 9216
#define T_KH 18432
#define T_KL 27648
#define T_VH 36864
#define T_VL 46080
#define T_W  55296            // 64 x 88 halves = 11264
#define T_ZR 66560
#define T_ZM 67072
#define SMEM_TOTAL 67584

// pos prepass smem
#define P_QH  0
#define P_QL  9216
#define P_PEH 18432           // 64 x 272B
#define P_PEL 35840
#define PSMEM 53248

#define QN (64*1024*64)
#define KN (64*2048*64)

typedef uint32_t u32;

__device__ __align__(16) __nv_bfloat16 gQh[QN], gQl[QN];
__device__ __align__(16) __nv_bfloat16 gKh[KN], gKl[KN];
__device__ __align__(16) __nv_bfloat16 gVh[KN], gVl[KN];
__device__ __align__(16) __nv_bfloat16 gPh[65536], gPl[65536];
__device__ __align__(16) __half gPOS[65536ull * PSTR + 64];   // fp16 pos, padded

__device__ __forceinline__ u32 hi2(float a, float b) {
    u32 r;
    asm("prmt.b32 %0, %1, %2, 0x7632;"
        : "=r"(r) : "r"(__float_as_uint(a)), "r"(__float_as_uint(b)));
    return r;
}
__device__ __forceinline__ float flo(float x) {
    return x - __int_as_float(__float_as_int(x) & 0xffff0000);
}
__device__ __forceinline__ u32 lo2(float a, float b) {
    __nv_bfloat162 t = __floats2bfloat162_rn(flo(a), flo(b));
    return *reinterpret_cast<u32*>(&t);
}
__device__ __forceinline__ void mma(float* c, const u32* a, const u32* b) {
    asm volatile("mma.sync.aligned.m16n8k16.row.col.f32.bf16.bf16.f32 "
        "{%0,%1,%2,%3}, {%4,%5,%6,%7}, {%8,%9}, {%0,%1,%2,%3};"
        : "+f"(c[0]), "+f"(c[1]), "+f"(c[2]), "+f"(c[3])
        : "r"(a[0]), "r"(a[1]), "r"(a[2]), "r"(a[3]), "r"(b[0]), "r"(b[1]));
}
__device__ __forceinline__ void ldsm4(u32* r, u32 a) {
    asm volatile("ldmatrix.sync.aligned.m8n8.x4.shared.b16 {%0,%1,%2,%3}, [%4];"
        : "=r"(r[0]), "=r"(r[1]), "=r"(r[2]), "=r"(r[3]) : "r"(a));
}
__device__ __forceinline__ void ldsm4t(u32* r, u32 a) {
    asm volatile("ldmatrix.sync.aligned.m8n8.x4.trans.shared.b16 {%0,%1,%2,%3}, [%4];"
        : "=r"(r[0]), "=r"(r[1]), "=r"(r[2]), "=r"(r[3]) : "r"(a));
}
__device__ __forceinline__ u32 smem_u32(const void* p) {
    u32 a;
    asm("{ .reg .u64 t; cvta.to.shared.u64 t, %1; cvt.u32.u64 %0, t; }" : "=r"(a) : "l"(p));
    return a;
}
__device__ __forceinline__ void cp16(u32 dst, const void* src) {
    unsigned long long g = (unsigned long long)__cvta_generic_to_global(src);
    asm volatile("cp.async.cg.shared.global [%0], [%1], 16;" :: "r"(dst), "l"(g) : "memory");
}
#define CP_COMMIT() asm volatile("cp.async.commit_group;" ::: "memory")
#define CP_WAIT0()  asm volatile("cp.async.wait_group 0;" ::: "memory")
#define CP_WAIT1()  asm volatile("cp.async.wait_group 1;" ::: "memory")

// ---------------- prepass 1: f32 -> bf16 hi/lo split ----------------
__global__ __launch_bounds__(256)
void cvt_pre(const float* __restrict__ q, const float* __restrict__ k,
             const float* __restrict__ v, const float* __restrict__ pe)
{
    size_t i = (size_t)blockIdx.x * 256 + threadIdx.x;   // float4 index
    const float4* s; uint2 *dh, *dl; size_t j;
    if (i < 1048576ull)      { s = (const float4*)q;  dh = (uint2*)gQh; dl = (uint2*)gQl; j = i; }
    else if (i < 3145728ull) { s = (const float4*)k;  dh = (uint2*)gKh; dl = (uint2*)gKl; j = i - 1048576ull; }
    else if (i < 5242880ull) { s = (const float4*)v;  dh = (uint2*)gVh; dl = (uint2*)gVl; j = i - 3145728ull; }
    else if (i < 5259264ull) { s = (const float4*)pe; dh = (uint2*)gPh; dl = (uint2*)gPl; j = i - 5242880ull; }
    else return;
    float4 x = s[j];
    dh[j] = make_uint2(hi2(x.x, x.y), hi2(x.z, x.w));
    dl[j] = make_uint2(lo2(x.x, x.y), lo2(x.z, x.w));
}

// ---------------- prepass 2: POS[bh][m][l] = Q . PE (dense, fp16 out) ----------------
__global__ __launch_bounds__(256)
void pos_pre()
{
    extern __shared__ char smem[];
    const int tid = threadIdx.x;
    const int lane = tid & 31, w = tid >> 5;
    const int g = lane >> 2, tig = lane & 3;
    const int lr = lane & 7, qd = lane >> 3;
    const int wr = w & 3, wc = w >> 2;
    const int r0 = wr * 16, cbl = wc * 64;
    const int bh = blockIdx.y;
    const int m0 = (blockIdx.x & 15) * 64;
    const int l0 = (blockIdx.x >> 4) * 128;
    const u32 sb = smem_u32(smem);

    {   // Q 64x64 hi/lo + PE 64x128 hi/lo via cp.async
        const size_t qoff = ((size_t)bh * 1024 + m0) * 64;
        #pragma unroll
        for (int t = 0; t < 2; t++) {
            int idx = tid + t * 256;
            int r = idx >> 3, s = idx & 7;
            u32 so = (u32)(r * STRB + s * 16);
            size_t go = qoff + (size_t)r * 64 + s * 8;
            cp16(sb + P_QH + so, gQh + go);
            cp16(sb + P_QL + so, gQl + go);
        }
        #pragma unroll
        for (int t = 0; t < 4; t++) {
            int idx = tid + t * 256;
            int d = idx >> 4, s = idx & 15;
            u32 so = (u32)(d * 272 + s * 16);
            size_t go = (size_t)d * 1024 + l0 + s * 8;
            cp16(sb + P_PEH + so, gPh + go);
            cp16(sb + P_PEL + so, gPl + go);
        }
        CP_COMMIT(); CP_WAIT0();
    }
    __syncthreads();

    const u32 baseQ  = sb + P_QH + (u32)((r0 + (qd & 1) * 8 + lr) * STRB) + (u32)((qd >> 1) * 16);
    const u32 basePE = sb + ((qd < 2) ? P_PEH : P_PEL) + (u32)(((qd & 1) * 8 + lr) * 272) + (u32)(cbl * 2);

    float cs[8][4];
    #pragma unroll
    for (int nt = 0; nt < 8; nt++)
        cs[nt][0] = cs[nt][1] = cs[nt][2] = cs[nt][3] = 0.f;
    #pragma unroll
    for (int kt = 0; kt < 4; kt++) {
        u32 ah[4], al[4];
        ldsm4(ah, baseQ + kt * 32);
        ldsm4(al, baseQ + (P_QL - P_QH) + kt * 32);
        #pragma unroll
        for (int nt = 0; nt < 8; nt++) {
            u32 f[4];
            ldsm4t(f, basePE + kt * (16 * 272) + nt * 16);
            mma(cs[nt], ah, f);
            mma(cs[nt], ah, f + 2);
            mma(cs[nt], al, f);
        }
    }
    const size_t rowg = (size_t)bh * 1024 + m0 + r0 + g;
    #pragma unroll
    for (int nt = 0; nt < 8; nt++) {
        int jc = l0 + cbl + nt * 8 + tig * 2;
        *(__half2*)&gPOS[rowg * PSTR + 64 + jc] = __floats2half2_rn(cs[nt][0], cs[nt][1]);
        *(__half2*)&gPOS[(rowg + 8) * PSTR + 64 + jc] = __floats2half2_rn(cs[nt][2], cs[nt][3]);
    }
}

// ---------------- main kernel ----------------
__global__ __launch_bounds__(256, 2)
void seqattn_mma(const float* __restrict__ cval, float* __restrict__ out)
{
    extern __shared__ char smem[];
    __half* W = (__half*)(smem + T_W);

    const int tid = threadIdx.x;
    const int lane = tid & 31, w = tid >> 5;
    const int g = lane >> 2, tig = lane & 3;
    const int wr = w & 3, wc = w >> 2;
    const int r0 = wr * 16;             // row strip base
    const int cb = wc * 32;             // key/col strip base
    const int lr = lane & 7, qd = lane >> 3;

    const int bh = blockIdx.y, m0 = blockIdx.x * 64;
    const float cvL  = cval[bh & 7] * 1024.0f;
    const float madd = (cvL - 1023.0f) * 0.03125f + 1.0f;

    const u32 sb = smem_u32(smem);
    const u32 baseQh = sb + T_QH + (u32)((r0 + (qd & 1) * 8 + lr) * STRB) + (u32)((qd >> 1) * 16);
    const u32 baseK  = sb + ((qd < 2) ? T_KH : T_KL) + (u32)((cb + lr) * STRB) + (u32)((qd & 1) * 16);
    const u32 baseV  = sb + ((qd < 2) ? T_VH : T_VL) + (u32)((cb + (qd & 1) * 8 + lr) * STRB);

    // copy-seg coords (512 segs per 64x64 tile, 2/thread)
    const int row0 = tid >> 3, s0 = tid & 7;
    const int row1 = row0 + 32;
    const u32 so0 = (u32)(row0 * STRB + s0 * 16);
    const u32 so1 = (u32)(row1 * STRB + s0 * 16);
    const size_t go0 = (size_t)row0 * 64 + s0 * 8;
    const size_t go1 = (size_t)row1 * 64 + s0 * 8;

    // ---- Q tiles ----
    {
        const size_t qoff = ((size_t)bh * 1024 + m0) * 64;
        cp16(sb + T_QH + so0, gQh + qoff + go0);
        cp16(sb + T_QH + so1, gQh + qoff + go1);
        cp16(sb + T_QL + so0, gQl + qoff + go0);
        cp16(sb + T_QL + so1, gQl + qoff + go1);
        CP_COMMIT(); CP_WAIT0();
    }
    __syncthreads();

    u32 qfh[4][4], qfl[4][4];
    #pragma unroll
    for (int kt = 0; kt < 4; kt++) {
        ldsm4(qfh[kt], baseQh + kt * 32);
        ldsm4(qfl[kt], baseQh + (T_QL - T_QH) + kt * 32);
    }

    float o[8][4];
    #pragma unroll
    for (int i = 0; i < 8; i++) { o[i][0] = o[i][1] = o[i][2] = o[i][3] = 0.f; }
    float zr0 = 0.f, zr1 = 0.f, zm0 = 0.f, zm1 = 0.f;

    #pragma unroll 1
    for (int c = 0; c < 17; c++) {
        const int n0 = m0 + c * 64, l0 = c * 64;

        __syncthreads();   // prev chunk's smem consumers done

        const size_t kvo = ((size_t)bh * 2048 + n0) * 64;
        // group A: K
        cp16(sb + T_KH + so0, gKh + kvo + go0);
        cp16(sb + T_KH + so1, gKh + kvo + go1);
        cp16(sb + T_KL + so0, gKl + kvo + go0);
        cp16(sb + T_KL + so1, gKl + kvo + go1);
        CP_COMMIT();
        // group B: V + POS window
        cp16(sb + T_VH + so0, gVh + kvo + go0);
        cp16(sb + T_VH + so1, gVh + kvo + go1);
        cp16(sb + T_VL + so0, gVl + kvo + go0);
        cp16(sb + T_VL + so1, gVl + kvo + go1);
        #pragma unroll
        for (int t = 0; t < 3; t++) {
            int idx = tid + t * 256;
            if (idx < 640) {
                int row = idx / 10;
                int si = idx - row * 10;
                int a = (l0 - row) & ~7;
                size_t src = (size_t)(bh * 1024 + m0 + row) * PSTR + 64 + a + si * 8;
                cp16(sb + T_W + (u32)(row * (WSTR * 2) + si * 16), gPOS + src);
            }
        }
        CP_COMMIT();
        CP_WAIT1();        // K landed (V/POS may still fly)
        __syncthreads();

        // ---- S = Q . K^T ----
        float cs[4][4];
        #pragma unroll
        for (int nt = 0; nt < 4; nt++)
            cs[nt][0] = cs[nt][1] = cs[nt][2] = cs[nt][3] = 0.f;
        #pragma unroll
        for (int nt = 0; nt < 4; nt++) {
            #pragma unroll
            for (int kt = 0; kt < 4; kt++) {
                u32 f[4];
                ldsm4(f, baseK + nt * 1152 + kt * 32);
                mma(cs[nt], qfh[kt], f);
                mma(cs[nt], qfh[kt], f + 2);
                mma(cs[nt], qfl[kt], f);
            }
        }
        CP_WAIT0();        // V + POS landed
        __syncthreads();

        // ---- scoring: exp2 poly + span mask, deferred normalization ----
        const int wo = (l0 - (r0 + g)) & 7;
        const int wbase = (r0 + g) * WSTR + wo;
        #pragma unroll
        for (int nt = 0; nt < 4; nt++) {
            #pragma unroll
            for (int e = 0; e < 4; e++) {
                int rr = r0 + g + (e & 2) * 4;
                int jj = cb + nt * 8 + tig * 2 + (e & 1);
                int l  = l0 + jj - rr;
                float pos = __half2float(W[wbase + ((e & 2) ? 8 * WSTR : 0) + jj]);
                float y = (cs[nt][e] + pos) * CEXP;
                float t0 = y + 12582912.f;
                float f = y - (t0 - 12582912.f);
                int ni23 = __float_as_int(t0) << 23;
                float p = fmaf(f, 1.3333558146e-3f, 9.6181291076e-3f);
                p = fmaf(f, p, 5.5504108664e-2f);
                p = fmaf(f, p, 2.4022650696e-1f);
                p = fmaf(f, p, 6.9314718056e-1f);
                p = fmaf(f, p, 1.0f);
                float ev = __int_as_float(__float_as_int(p) + ni23);
                bool ok = ((unsigned)l < 1024u);
                ev = ok ? ev : 0.f;
                float mk = fminf(fmaxf(fmaf((float)l, 0.03125f, madd), 0.f), 1.f);
                float pm = ev * mk;
                if (e & 2) { zr1 += ev; zm1 += pm; }
                else       { zr0 += ev; zm0 += pm; }
                cs[nt][e] = pm;
            }
        }

        // ---- pack P into A-fragments ----
        u32 pfh[2][4], pfl[2][4];
        #pragma unroll
        for (int k2 = 0; k2 < 2; k2++) {
            pfh[k2][0] = hi2(cs[2*k2][0], cs[2*k2][1]);
            pfh[k2][1] = hi2(cs[2*k2][2], cs[2*k2][3]);
            pfh[k2][2] = hi2(cs[2*k2+1][0], cs[2*k2+1][1]);
            pfh[k2][3] = hi2(cs[2*k2+1][2], cs[2*k2+1][3]);
            pfl[k2][0] = lo2(cs[2*k2][0], cs[2*k2][1]);
            pfl[k2][1] = lo2(cs[2*k2][2], cs[2*k2][3]);
            pfl[k2][2] = lo2(cs[2*k2+1][0], cs[2*k2+1][1]);
            pfl[k2][3] = lo2(cs[2*k2+1][2], cs[2*k2+1][3]);
        }

        // ---- O += P . V ----
        #pragma unroll
        for (int nt = 0; nt < 8; nt++) {
            #pragma unroll
            for (int k2 = 0; k2 < 2; k2++) {
                u32 f[4];
                ldsm4t(f, baseV + k2 * 2304 + nt * 16);
                mma(o[nt], pfh[k2], f);
                mma(o[nt], pfh[k2], f + 2);
                mma(o[nt], pfl[k2], f);
            }
        }
    }

    // ---------------- epilogue ----------------
    __syncthreads();
    zr0 += __shfl_xor_sync(0xffffffffu, zr0, 1); zr0 += __shfl_xor_sync(0xffffffffu, zr0, 2);
    zr1 += __shfl_xor_sync(0xffffffffu, zr1, 1); zr1 += __shfl_xor_sync(0xffffffffu, zr1, 2);
    zm0 += __shfl_xor_sync(0xffffffffu, zm0, 1); zm0 += __shfl_xor_sync(0xffffffffu, zm0, 2);
    zm1 += __shfl_xor_sync(0xffffffffu, zm1, 1); zm1 += __shfl_xor_sync(0xffffffffu, zm1, 2);
    float* ZR = (float*)(smem + T_ZR);
    float* ZM = (float*)(smem + T_ZM);
    if (tig == 0) {
        ZR[wc * 64 + r0 + g] = zr0;  ZR[wc * 64 + r0 + g + 8] = zr1;
        ZM[wc * 64 + r0 + g] = zm0;  ZM[wc * 64 + r0 + g + 8] = zm1;
    }
    float* Ob = (float*)(smem + (wc ? 18432 : 0));
    #pragma unroll
    for (int nt = 0; nt < 8; nt++) {
        int d = 8 * nt + tig * 2;
        Ob[(r0 + g) * OSTR + d]         = o[nt][0];
        Ob[(r0 + g) * OSTR + d + 1]     = o[nt][1];
        Ob[(r0 + g + 8) * OSTR + d]     = o[nt][2];
        Ob[(r0 + g + 8) * OSTR + d + 1] = o[nt][3];
    }
    __syncthreads();
    float* A = (float*)smem;
    float* B = (float*)(smem + 18432);
    #pragma unroll
    for (int t = 0; t < 4; t++) {
        int idx = tid + t * 256;
        int r = idx >> 4, d4 = (idx & 15) * 4;
        float inv = 1.f / ((ZM[r] + ZM[64 + r]) + 1e-8f * (ZR[r] + ZR[64 + r]));
        float4 a = *(float4*)&A[r * OSTR + d4];
        float4 b = *(float4*)&B[r * OSTR + d4];
        float4 ov = make_float4((a.x + b.x) * inv, (a.y + b.y) * inv,
                                (a.z + b.z) * inv, (a.w + b.w) * inv);
        *(float4*)&out[((size_t)bh * 1024 + m0 + r) * 64 + d4] = ov;
    }
}

extern "C" void kernel_launch(void* const* d_in, const int* in_sizes, int n_in,
                              void* d_out, int out_size)
{
    (void)in_sizes; (void)n_in; (void)out_size;
    const float* q  = (const float*)d_in[0];
    const float* k  = (const float*)d_in[1];
    const float* v  = (const float*)d_in[2];
    const float* pe = (const float*)d_in[3];
    const float* cv = (const float*)d_in[4];

    cvt_pre<<<20544, 256>>>(q, k, v, pe);

    cudaFuncSetAttribute(pos_pre, cudaFuncAttributeMaxDynamicSharedMemorySize, PSMEM);
    pos_pre<<<dim3(128, 64), 256, PSMEM>>>();

    cudaFuncSetAttribute(seqattn_mma, cudaFuncAttributeMaxDynamicSharedMemorySize, SMEM_TOTAL);
    dim3 grid(16, 64);
    seqattn_mma<<<grid, 256, SMEM_TOTAL>>>(cv, (float*)d_out);
}

// round 15
// speedup vs baseline: 1.4106x; 1.4106x over previous
#include <cuda_runtime.h>
#include <cuda_fp16.h>
#include <stdint.h>

#define STRB 144              // smem tile row stride, bytes
#define CEXP 0.06375846855f   // (1/sqrt(512)) * log2(e)
#define RSTR 132              // ring row stride (f32)
#define OSTR 68               // epilogue O-buf row stride (f32)

// smem byte offsets (tiles 64 rows x 144 B)
#define T_QH   0
#define T_KH   9216
#define T_KL   18432
#define T_VH   27648
#define T_VL   36864
#define T_PEH  46080
#define T_PEL  55296
#define T_RING 64512          // f32 ring 64x132 = 33792; epilogue: 2 O-bufs
#define T_ZR   98304
#define T_ZM   98816
#define SMEM_TOTAL 99328      // x2 CTAs = 194 KB/SM

#define QN (64*1024*64)
#define KN (64*2048*64)

typedef uint32_t u32;

// pre-converted fp16 hi/lo operand buffers (scratch via __device__ globals)
__device__ __align__(16) __half gQh[QN];
__device__ __align__(16) __half gKh[KN], gKl[KN];
__device__ __align__(16) __half gVh[KN], gVl[KN];
__device__ __align__(16) __half gPh[65536], gPl[65536];

__device__ __forceinline__ u32 h2(float a, float b) {
    __half2 t = __floats2half2_rn(a, b);
    return *reinterpret_cast<u32*>(&t);
}
__device__ __forceinline__ u32 l2h(float a, float b) {
    float ra = a - __half2float(__float2half_rn(a));
    float rb = b - __half2float(__float2half_rn(b));
    __half2 t = __floats2half2_rn(ra, rb);
    return *reinterpret_cast<u32*>(&t);
}
__device__ __forceinline__ void mma(float* c, const u32* a, const u32* b) {
    asm volatile("mma.sync.aligned.m16n8k16.row.col.f32.f16.f16.f32 "
        "{%0,%1,%2,%3}, {%4,%5,%6,%7}, {%8,%9}, {%0,%1,%2,%3};"
        : "+f"(c[0]), "+f"(c[1]), "+f"(c[2]), "+f"(c[3])
        : "r"(a[0]), "r"(a[1]), "r"(a[2]), "r"(a[3]), "r"(b[0]), "r"(b[1]));
}
__device__ __forceinline__ void ldsm4(u32* r, u32 a) {
    asm volatile("ldmatrix.sync.aligned.m8n8.x4.shared.b16 {%0,%1,%2,%3}, [%4];"
        : "=r"(r[0]), "=r"(r[1]), "=r"(r[2]), "=r"(r[3]) : "r"(a));
}
__device__ __forceinline__ void ldsm4t(u32* r, u32 a) {
    asm volatile("ldmatrix.sync.aligned.m8n8.x4.trans.shared.b16 {%0,%1,%2,%3}, [%4];"
        : "=r"(r[0]), "=r"(r[1]), "=r"(r[2]), "=r"(r[3]) : "r"(a));
}
__device__ __forceinline__ u32 smem_u32(const void* p) {
    u32 a;
    asm("{ .reg .u64 t; cvta.to.shared.u64 t, %1; cvt.u32.u64 %0, t; }" : "=r"(a) : "l"(p));
    return a;
}
__device__ __forceinline__ void cp16(u32 dst, const void* src) {
    unsigned long long g = (unsigned long long)__cvta_generic_to_global(src);
    asm volatile("cp.async.cg.shared.global [%0], [%1], 16;" :: "r"(dst), "l"(g) : "memory");
}
#define CP_COMMIT() asm volatile("cp.async.commit_group;" ::: "memory")
#define CP_WAIT0()  asm volatile("cp.async.wait_group 0;" ::: "memory")
#define CP_WAIT1()  asm volatile("cp.async.wait_group 1;" ::: "memory")

// ---------------- prepass: f32 -> fp16 hi (+lo for K/V/PE) ----------------
__global__ __launch_bounds__(256)
void cvt_pre(const float* __restrict__ q, const float* __restrict__ k,
             const float* __restrict__ v, const float* __restrict__ pe)
{
    size_t i = (size_t)blockIdx.x * 256 + threadIdx.x;   // float4 index
    if (i < 1048576ull) {            // Q: hi only (2-term GEMMs use qh with full K/PE)
        float4 x = ((const float4*)q)[i];
        ((uint2*)gQh)[i] = make_uint2(h2(x.x, x.y), h2(x.z, x.w));
        return;
    }
    const float4* s; uint2 *dh, *dl; size_t j;
    if (i < 3145728ull)      { s = (const float4*)k;  dh = (uint2*)gKh; dl = (uint2*)gKl; j = i - 1048576ull; }
    else if (i < 5242880ull) { s = (const float4*)v;  dh = (uint2*)gVh; dl = (uint2*)gVl; j = i - 3145728ull; }
    else if (i < 5259264ull) { s = (const float4*)pe; dh = (uint2*)gPh; dl = (uint2*)gPl; j = i - 5242880ull; }
    else return;
    float4 x = s[j];
    dh[j] = make_uint2(h2(x.x, x.y), h2(x.z, x.w));
    dl[j] = make_uint2(l2h(x.x, x.y), l2h(x.z, x.w));
}

// ---------------- main kernel ----------------
__global__ __launch_bounds__(256, 2)
void seqattn_mma(const float* __restrict__ cval, float* __restrict__ out)
{
    extern __shared__ char smem[];
    float* ring = (float*)(smem + T_RING);

    const int tid = threadIdx.x;
    const int lane = tid & 31, w = tid >> 5;
    const int g = lane >> 2, tig = lane & 3;
    const int wr = w & 3, wc = w >> 2;
    const int r0 = wr * 16;             // row strip base
    const int cb = wc * 32;             // key/col strip base
    const int lr = lane & 7, qd = lane >> 3;

    const int bh = blockIdx.y, m0 = blockIdx.x * 64;
    const float cvL  = cval[bh & 7] * 1024.0f;
    const float madd = (cvL - 1023.0f) * 0.03125f + 1.0f;

    const u32 sb = smem_u32(smem);
    const u32 baseQh = sb + T_QH + (u32)((r0 + (qd & 1) * 8 + lr) * STRB) + (u32)((qd >> 1) * 16);
    const u32 baseK  = sb + ((qd < 2) ? T_KH  : T_KL)  + (u32)((cb + lr) * STRB) + (u32)((qd & 1) * 16);
    const u32 baseV  = sb + ((qd < 2) ? T_VH  : T_VL)  + (u32)((cb + (qd & 1) * 8 + lr) * STRB);
    const u32 basePE = sb + ((qd < 2) ? T_PEH : T_PEL) + (u32)(((qd & 1) * 8 + lr) * STRB) + (u32)(cb * 2);

    // copy-seg coords (512 segs per 64x64 tile, 2/thread)
    const int row0 = tid >> 3, s0 = tid & 7;
    const int row1 = row0 + 32;
    const u32 so0 = (u32)(row0 * STRB + s0 * 16);
    const u32 so1 = (u32)(row1 * STRB + s0 * 16);
    const size_t go0 = (size_t)row0 * 64 + s0 * 8;
    const size_t go1 = (size_t)row1 * 64 + s0 * 8;

    // ---- Q tile (hi only) ----
    {
        const size_t qoff = ((size_t)bh * 1024 + m0) * 64;
        cp16(sb + T_QH + so0, gQh + qoff + go0);
        cp16(sb + T_QH + so1, gQh + qoff + go1);
        CP_COMMIT(); CP_WAIT0();
    }
    __syncthreads();

    u32 qfh[4][4];
    #pragma unroll
    for (int kt = 0; kt < 4; kt++)
        ldsm4(qfh[kt], baseQh + kt * 32);

    float o[8][4];
    #pragma unroll
    for (int i = 0; i < 8; i++) { o[i][0] = o[i][1] = o[i][2] = o[i][3] = 0.f; }
    float zr0 = 0.f, zr1 = 0.f, zm0 = 0.f, zm1 = 0.f;

    #pragma unroll 1
    for (int c = 0; c < 17; c++) {
        const int n0 = m0 + c * 64, l0 = c * 64;

        __syncthreads();   // prev chunk's smem consumers done

        const size_t kvo = ((size_t)bh * 2048 + n0) * 64;
        // group A: K (+PE)
        cp16(sb + T_KH + so0, gKh + kvo + go0);
        cp16(sb + T_KH + so1, gKh + kvo + go1);
        cp16(sb + T_KL + so0, gKl + kvo + go0);
        cp16(sb + T_KL + so1, gKl + kvo + go1);
        if (l0 < 1024) {   // PE rows are d (stride 1024 elems)
            cp16(sb + T_PEH + so0, gPh + (size_t)row0 * 1024 + l0 + s0 * 8);
            cp16(sb + T_PEH + so1, gPh + (size_t)row1 * 1024 + l0 + s0 * 8);
            cp16(sb + T_PEL + so0, gPl + (size_t)row0 * 1024 + l0 + s0 * 8);
            cp16(sb + T_PEL + so1, gPl + (size_t)row1 * 1024 + l0 + s0 * 8);
        }
        CP_COMMIT();
        // group B: V
        cp16(sb + T_VH + so0, gVh + kvo + go0);
        cp16(sb + T_VH + so1, gVh + kvo + go1);
        cp16(sb + T_VL + so0, gVl + kvo + go0);
        cp16(sb + T_VL + so1, gVl + kvo + go1);
        CP_COMMIT();
        CP_WAIT1();        // K+PE landed (V may still fly)
        __syncthreads();

        float cs[4][4];
        // ---- POS = qh . (PEh + PEl), trans ldsm ----
        if (l0 < 1024) {
            #pragma unroll
            for (int nt = 0; nt < 4; nt++)
                cs[nt][0] = cs[nt][1] = cs[nt][2] = cs[nt][3] = 0.f;
            #pragma unroll
            for (int nt = 0; nt < 4; nt++) {
                #pragma unroll
                for (int kt = 0; kt < 4; kt++) {
                    u32 f[4];
                    ldsm4t(f, basePE + kt * 2304 + nt * 16);
                    mma(cs[nt], qfh[kt], f);
                    mma(cs[nt], qfh[kt], f + 2);
                }
            }
            int slot = (c & 1) * 64;
            #pragma unroll
            for (int nt = 0; nt < 4; nt++) {
                int jl = cb + 8 * nt + tig * 2;
                ring[(r0 + g) * RSTR + slot + jl]         = cs[nt][0];
                ring[(r0 + g) * RSTR + slot + jl + 1]     = cs[nt][1];
                ring[(r0 + g + 8) * RSTR + slot + jl]     = cs[nt][2];
                ring[(r0 + g + 8) * RSTR + slot + jl + 1] = cs[nt][3];
            }
        }

        // ---- S = qh . (Kh + Kl)^T ----
        #pragma unroll
        for (int nt = 0; nt < 4; nt++)
            cs[nt][0] = cs[nt][1] = cs[nt][2] = cs[nt][3] = 0.f;
        #pragma unroll
        for (int nt = 0; nt < 4; nt++) {
            #pragma unroll
            for (int kt = 0; kt < 4; kt++) {
                u32 f[4];
                ldsm4(f, baseK + nt * 1152 + kt * 32);
                mma(cs[nt], qfh[kt], f);
                mma(cs[nt], qfh[kt], f + 2);
            }
        }
        CP_WAIT0();        // V landed
        __syncthreads();   // ring + V visible

        // ---- scoring: exp2 poly + span mask, deferred normalization ----
        #pragma unroll
        for (int nt = 0; nt < 4; nt++) {
            #pragma unroll
            for (int e = 0; e < 4; e++) {
                int rr = r0 + g + (e & 2) * 4;
                int j  = cb + nt * 8 + tig * 2 + (e & 1);
                int l  = l0 + j - rr;
                float pos = ring[rr * RSTR + (l & 127)];
                float y = (cs[nt][e] + pos) * CEXP;
                float t0 = y + 12582912.f;
                float f = y - (t0 - 12582912.f);
                int ni23 = __float_as_int(t0) << 23;
                float p = fmaf(f, 1.3333558146e-3f, 9.6181291076e-3f);
                p = fmaf(f, p, 5.5504108664e-2f);
                p = fmaf(f, p, 2.4022650696e-1f);
                p = fmaf(f, p, 6.9314718056e-1f);
                p = fmaf(f, p, 1.0f);
                float ev = __int_as_float(__float_as_int(p) + ni23);
                bool ok = ((unsigned)l < 1024u);
                ev = ok ? ev : 0.f;
                float mk = fminf(fmaxf(fmaf((float)l, 0.03125f, madd), 0.f), 1.f);
                float pm = ev * mk;
                if (e & 2) { zr1 += ev; zm1 += pm; }
                else       { zr0 += ev; zm0 += pm; }
                cs[nt][e] = pm;
            }
        }

        // ---- pack P into fp16 A-fragments (single operand, no split) ----
        u32 pf[2][4];
        #pragma unroll
        for (int k2 = 0; k2 < 2; k2++) {
            pf[k2][0] = h2(cs[2*k2][0], cs[2*k2][1]);
            pf[k2][1] = h2(cs[2*k2][2], cs[2*k2][3]);
            pf[k2][2] = h2(cs[2*k2+1][0], cs[2*k2+1][1]);
            pf[k2][3] = h2(cs[2*k2+1][2], cs[2*k2+1][3]);
        }

        // ---- O += P16 . (Vh + Vl) ----
        #pragma unroll
        for (int nt = 0; nt < 8; nt++) {
            #pragma unroll
            for (int k2 = 0; k2 < 2; k2++) {
                u32 f[4];
                ldsm4t(f, baseV + k2 * 2304 + nt * 16);
                mma(o[nt], pf[k2], f);
                mma(o[nt], pf[k2], f + 2);
            }
        }
    }

    // ---------------- epilogue ----------------
    __syncthreads();   // last ring reads done; reuse tile region as O-bufs
    zr0 += __shfl_xor_sync(0xffffffffu, zr0, 1); zr0 += __shfl_xor_sync(0xffffffffu, zr0, 2);
    zr1 += __shfl_xor_sync(0xffffffffu, zr1, 1); zr1 += __shfl_xor_sync(0xffffffffu, zr1, 2);
    zm0 += __shfl_xor_sync(0xffffffffu, zm0, 1); zm0 += __shfl_xor_sync(0xffffffffu, zm0, 2);
    zm1 += __shfl_xor_sync(0xffffffffu, zm1, 1); zm1 += __shfl_xor_sync(0xffffffffu, zm1, 2);
    float* ZR = (float*)(smem + T_ZR);
    float* ZM = (float*)(smem + T_ZM);
    if (tig == 0) {
        ZR[wc * 64 + r0 + g] = zr0;  ZR[wc * 64 + r0 + g + 8] = zr1;
        ZM[wc * 64 + r0 + g] = zm0;  ZM[wc * 64 + r0 + g + 8] = zm1;
    }
    float* Ob = (float*)(smem + (wc ? 18432 : 0));
    #pragma unroll
    for (int nt = 0; nt < 8; nt++) {
        int d = 8 * nt + tig * 2;
        Ob[(r0 + g) * OSTR + d]         = o[nt][0];
        Ob[(r0 + g) * OSTR + d + 1]     = o[nt][1];
        Ob[(r0 + g + 8) * OSTR + d]     = o[nt][2];
        Ob[(r0 + g + 8) * OSTR + d + 1] = o[nt][3];
    }
    __syncthreads();
    float* A = (float*)smem;
    float* B = (float*)(smem + 18432);
    #pragma unroll
    for (int t = 0; t < 4; t++) {
        int idx = tid + t * 256;
        int r = idx >> 4, d4 = (idx & 15) * 4;
        float inv = 1.f / ((ZM[r] + ZM[64 + r]) + 1e-8f * (ZR[r] + ZR[64 + r]));
        float4 a = *(float4*)&A[r * OSTR + d4];
        float4 b = *(float4*)&B[r * OSTR + d4];
        float4 ov = make_float4((a.x + b.x) * inv, (a.y + b.y) * inv,
                                (a.z + b.z) * inv, (a.w + b.w) * inv);
        *(float4*)&out[((size_t)bh * 1024 + m0 + r) * 64 + d4] = ov;
    }
}

extern "C" void kernel_launch(void* const* d_in, const int* in_sizes, int n_in,
                              void* d_out, int out_size)
{
    (void)in_sizes; (void)n_in; (void)out_size;
    const float* q  = (const float*)d_in[0];
    const float* k  = (const float*)d_in[1];
    const float* v  = (const float*)d_in[2];
    const float* pe = (const float*)d_in[3];
    const float* cv = (const float*)d_in[4];

    cvt_pre<<<20544, 256>>>(q, k, v, pe);

    cudaFuncSetAttribute(seqattn_mma, cudaFuncAttributeMaxDynamicSharedMemorySize, SMEM_TOTAL);
    dim3 grid(16, 64);
    seqattn_mma<<<grid, 256, SMEM_TOTAL>>>(cv, (float*)d_out);
}

// round 16
// speedup vs baseline: 2.0429x; 1.4482x over previous
#include <cuda_runtime.h>
#include <cuda_fp16.h>
#include <stdint.h>

#define STRB 144              // smem tile row stride, bytes
#define CEXP 0.06375846855f   // (1/sqrt(512)) * log2(e)
#define RSTR 132              // ring row stride (f32)
#define OSTR 68               // epilogue O-buf row stride (f32)

// smem byte offsets (tiles 64 rows x 144 B)
#define T_QH   0
#define T_KH   9216
#define T_VH   18432
#define T_PEH  27648
#define T_RING 36864          // f32 ring 64x132 = 33792
#define T_ZR   70656
#define T_ZM   71168
#define SMEM_TOTAL 71680      // x2 CTAs = 140 KB/SM

#define QN (64*1024*64)
#define KN (64*2048*64)

typedef uint32_t u32;

// pre-converted fp16 operand buffers (scratch via __device__ globals)
__device__ __align__(16) __half gQh[QN];
__device__ __align__(16) __half gKh[KN];
__device__ __align__(16) __half gVh[KN];
__device__ __align__(16) __half gPh[65536];

__device__ __forceinline__ u32 h2(float a, float b) {
    __half2 t = __floats2half2_rn(a, b);
    return *reinterpret_cast<u32*>(&t);
}
__device__ __forceinline__ void mma(float* c, const u32* a, const u32* b) {
    asm volatile("mma.sync.aligned.m16n8k16.row.col.f32.f16.f16.f32 "
        "{%0,%1,%2,%3}, {%4,%5,%6,%7}, {%8,%9}, {%0,%1,%2,%3};"
        : "+f"(c[0]), "+f"(c[1]), "+f"(c[2]), "+f"(c[3])
        : "r"(a[0]), "r"(a[1]), "r"(a[2]), "r"(a[3]), "r"(b[0]), "r"(b[1]));
}
__device__ __forceinline__ void ldsm4(u32* r, u32 a) {
    asm volatile("ldmatrix.sync.aligned.m8n8.x4.shared.b16 {%0,%1,%2,%3}, [%4];"
        : "=r"(r[0]), "=r"(r[1]), "=r"(r[2]), "=r"(r[3]) : "r"(a));
}
__device__ __forceinline__ void ldsm4t(u32* r, u32 a) {
    asm volatile("ldmatrix.sync.aligned.m8n8.x4.trans.shared.b16 {%0,%1,%2,%3}, [%4];"
        : "=r"(r[0]), "=r"(r[1]), "=r"(r[2]), "=r"(r[3]) : "r"(a));
}
__device__ __forceinline__ u32 smem_u32(const void* p) {
    u32 a;
    asm("{ .reg .u64 t; cvta.to.shared.u64 t, %1; cvt.u32.u64 %0, t; }" : "=r"(a) : "l"(p));
    return a;
}
__device__ __forceinline__ void cp16(u32 dst, const void* src) {
    unsigned long long g = (unsigned long long)__cvta_generic_to_global(src);
    asm volatile("cp.async.cg.shared.global [%0], [%1], 16;" :: "r"(dst), "l"(g) : "memory");
}
#define CP_COMMIT() asm volatile("cp.async.commit_group;" ::: "memory")
#define CP_WAIT0()  asm volatile("cp.async.wait_group 0;" ::: "memory")
#define CP_WAIT1()  asm volatile("cp.async.wait_group 1;" ::: "memory")

// ---------------- prepass: f32 -> fp16 ----------------
__global__ __launch_bounds__(256)
void cvt_pre(const float* __restrict__ q, const float* __restrict__ k,
             const float* __restrict__ v, const float* __restrict__ pe)
{
    size_t i = (size_t)blockIdx.x * 256 + threadIdx.x;   // float4 index
    const float4* s; uint2* d; size_t j;
    if (i < 1048576ull)      { s = (const float4*)q;  d = (uint2*)gQh; j = i; }
    else if (i < 3145728ull) { s = (const float4*)k;  d = (uint2*)gKh; j = i - 1048576ull; }
    else if (i < 5242880ull) { s = (const float4*)v;  d = (uint2*)gVh; j = i - 3145728ull; }
    else if (i < 5259264ull) { s = (const float4*)pe; d = (uint2*)gPh; j = i - 5242880ull; }
    else return;
    float4 x = s[j];
    d[j] = make_uint2(h2(x.x, x.y), h2(x.z, x.w));
}

// ---------------- main kernel ----------------
__global__ __launch_bounds__(256, 2)
void seqattn_mma(const float* __restrict__ cval, float* __restrict__ out)
{
    extern __shared__ char smem[];
    float* ring = (float*)(smem + T_RING);

    const int tid = threadIdx.x;
    const int lane = tid & 31, w = tid >> 5;
    const int g = lane >> 2, tig = lane & 3;
    const int wr = w & 3, wc = w >> 2;
    const int r0 = wr * 16;             // row strip base
    const int cb = wc * 32;             // key/col strip base
    const int lr = lane & 7, qd = lane >> 3;

    const int bh = blockIdx.y, m0 = blockIdx.x * 64;
    const float cvL  = cval[bh & 7] * 1024.0f;
    const float madd = (cvL - 1023.0f) * 0.03125f + 1.0f;

    const u32 sb = smem_u32(smem);
    // A-fragment base (Q)
    const u32 baseQh = sb + T_QH + (u32)((r0 + (qd & 1) * 8 + lr) * STRB) + (u32)((qd >> 1) * 16);
    // B-fragment bases: lanes 16-31 address the SECOND n-tile (x4 serves two tiles)
    const u32 baseK  = sb + T_KH  + (u32)((cb + (qd >> 1) * 8 + lr) * STRB) + (u32)((qd & 1) * 16);
    const u32 baseV  = sb + T_VH  + (u32)((cb + (qd & 1) * 8 + lr) * STRB) + (u32)((qd >> 1) * 16);
    const u32 basePE = sb + T_PEH + (u32)(((qd & 1) * 8 + lr) * STRB) + (u32)((qd >> 1) * 16) + (u32)(cb * 2);

    // copy-seg coords (512 segs per 64x64 tile, 2/thread)
    const int row0 = tid >> 3, s0 = tid & 7;
    const int row1 = row0 + 32;
    const u32 so0 = (u32)(row0 * STRB + s0 * 16);
    const u32 so1 = (u32)(row1 * STRB + s0 * 16);
    const size_t go0 = (size_t)row0 * 64 + s0 * 8;
    const size_t go1 = (size_t)row1 * 64 + s0 * 8;

    // ---- Q tile ----
    {
        const size_t qoff = ((size_t)bh * 1024 + m0) * 64;
        cp16(sb + T_QH + so0, gQh + qoff + go0);
        cp16(sb + T_QH + so1, gQh + qoff + go1);
        CP_COMMIT(); CP_WAIT0();
    }
    __syncthreads();

    u32 qfh[4][4];
    #pragma unroll
    for (int kt = 0; kt < 4; kt++)
        ldsm4(qfh[kt], baseQh + kt * 32);

    float o[8][4];
    #pragma unroll
    for (int i = 0; i < 8; i++) { o[i][0] = o[i][1] = o[i][2] = o[i][3] = 0.f; }
    float zr0 = 0.f, zr1 = 0.f, zm0 = 0.f, zm1 = 0.f;

    #pragma unroll 1
    for (int c = 0; c < 17; c++) {
        const int n0 = m0 + c * 64, l0 = c * 64;

        __syncthreads();   // prev chunk's smem consumers done

        const size_t kvo = ((size_t)bh * 2048 + n0) * 64;
        // group A: K (+PE)
        cp16(sb + T_KH + so0, gKh + kvo + go0);
        cp16(sb + T_KH + so1, gKh + kvo + go1);
        if (l0 < 1024) {   // PE rows are d (stride 1024 elems)
            cp16(sb + T_PEH + so0, gPh + (size_t)row0 * 1024 + l0 + s0 * 8);
            cp16(sb + T_PEH + so1, gPh + (size_t)row1 * 1024 + l0 + s0 * 8);
        }
        CP_COMMIT();
        // group B: V
        cp16(sb + T_VH + so0, gVh + kvo + go0);
        cp16(sb + T_VH + so1, gVh + kvo + go1);
        CP_COMMIT();
        CP_WAIT1();        // K+PE landed (V may still fly)
        __syncthreads();

        float cs[4][4];
        // ---- POS = qh . PEh (trans ldsm; one x4 feeds two n-tiles) ----
        if (l0 < 1024) {
            #pragma unroll
            for (int nt = 0; nt < 4; nt++)
                cs[nt][0] = cs[nt][1] = cs[nt][2] = cs[nt][3] = 0.f;
            #pragma unroll
            for (int ntp = 0; ntp < 2; ntp++) {
                #pragma unroll
                for (int kt = 0; kt < 4; kt++) {
                    u32 f[4];
                    ldsm4t(f, basePE + kt * (16 * STRB) + ntp * 32);
                    mma(cs[2*ntp],     qfh[kt], f);
                    mma(cs[2*ntp + 1], qfh[kt], f + 2);
                }
            }
            int slot = (c & 1) * 64;
            #pragma unroll
            for (int nt = 0; nt < 4; nt++) {
                int jl = cb + 8 * nt + tig * 2;
                ring[(r0 + g) * RSTR + slot + jl]         = cs[nt][0];
                ring[(r0 + g) * RSTR + slot + jl + 1]     = cs[nt][1];
                ring[(r0 + g + 8) * RSTR + slot + jl]     = cs[nt][2];
                ring[(r0 + g + 8) * RSTR + slot + jl + 1] = cs[nt][3];
            }
        }

        // ---- S = qh . Kh^T (one x4 feeds two n-tiles) ----
        #pragma unroll
        for (int nt = 0; nt < 4; nt++)
            cs[nt][0] = cs[nt][1] = cs[nt][2] = cs[nt][3] = 0.f;
        #pragma unroll
        for (int ntp = 0; ntp < 2; ntp++) {
            #pragma unroll
            for (int kt = 0; kt < 4; kt++) {
                u32 f[4];
                ldsm4(f, baseK + ntp * (16 * STRB) + kt * 32);
                mma(cs[2*ntp],     qfh[kt], f);
                mma(cs[2*ntp + 1], qfh[kt], f + 2);
            }
        }
        CP_WAIT0();        // V landed
        __syncthreads();   // ring + V visible

        // ---- scoring: exp2 poly + span mask, deferred normalization ----
        #pragma unroll
        for (int nt = 0; nt < 4; nt++) {
            #pragma unroll
            for (int e = 0; e < 4; e++) {
                int rr = r0 + g + (e & 2) * 4;
                int j  = cb + nt * 8 + tig * 2 + (e & 1);
                int l  = l0 + j - rr;
                float pos = ring[rr * RSTR + (l & 127)];
                float y = (cs[nt][e] + pos) * CEXP;
                float t0 = y + 12582912.f;
                float f = y - (t0 - 12582912.f);
                int ni23 = __float_as_int(t0) << 23;
                float p = fmaf(f, 1.3333558146e-3f, 9.6181291076e-3f);
                p = fmaf(f, p, 5.5504108664e-2f);
                p = fmaf(f, p, 2.4022650696e-1f);
                p = fmaf(f, p, 6.9314718056e-1f);
                p = fmaf(f, p, 1.0f);
                float ev = __int_as_float(__float_as_int(p) + ni23);
                bool ok = ((unsigned)l < 1024u);
                ev = ok ? ev : 0.f;
                float mk = fminf(fmaxf(fmaf((float)l, 0.03125f, madd), 0.f), 1.f);
                float pm = ev * mk;
                if (e & 2) { zr1 += ev; zm1 += pm; }
                else       { zr0 += ev; zm0 += pm; }
                cs[nt][e] = pm;
            }
        }

        // ---- pack P into fp16 A-fragments ----
        u32 pf[2][4];
        #pragma unroll
        for (int k2 = 0; k2 < 2; k2++) {
            pf[k2][0] = h2(cs[2*k2][0], cs[2*k2][1]);
            pf[k2][1] = h2(cs[2*k2][2], cs[2*k2][3]);
            pf[k2][2] = h2(cs[2*k2+1][0], cs[2*k2+1][1]);
            pf[k2][3] = h2(cs[2*k2+1][2], cs[2*k2+1][3]);
        }

        // ---- O += P16 . Vh (trans ldsm; one x4 feeds two d-tiles) ----
        #pragma unroll
        for (int ntp = 0; ntp < 4; ntp++) {
            #pragma unroll
            for (int k2 = 0; k2 < 2; k2++) {
                u32 f[4];
                ldsm4t(f, baseV + k2 * 2304 + ntp * 32);
                mma(o[2*ntp],     pf[k2], f);
                mma(o[2*ntp + 1], pf[k2], f + 2);
            }
        }
    }

    // ---------------- epilogue ----------------
    __syncthreads();   // last ring reads done; reuse tile region as O-bufs
    zr0 += __shfl_xor_sync(0xffffffffu, zr0, 1); zr0 += __shfl_xor_sync(0xffffffffu, zr0, 2);
    zr1 += __shfl_xor_sync(0xffffffffu, zr1, 1); zr1 += __shfl_xor_sync(0xffffffffu, zr1, 2);
    zm0 += __shfl_xor_sync(0xffffffffu, zm0, 1); zm0 += __shfl_xor_sync(0xffffffffu, zm0, 2);
    zm1 += __shfl_xor_sync(0xffffffffu, zm1, 1); zm1 += __shfl_xor_sync(0xffffffffu, zm1, 2);
    float* ZR = (float*)(smem + T_ZR);
    float* ZM = (float*)(smem + T_ZM);
    if (tig == 0) {
        ZR[wc * 64 + r0 + g] = zr0;  ZR[wc * 64 + r0 + g + 8] = zr1;
        ZM[wc * 64 + r0 + g] = zm0;  ZM[wc * 64 + r0 + g + 8] = zm1;
    }
    float* Ob = (float*)(smem + (wc ? 18432 : 0));
    #pragma unroll
    for (int nt = 0; nt < 8; nt++) {
        int d = 8 * nt + tig * 2;
        Ob[(r0 + g) * OSTR + d]         = o[nt][0];
        Ob[(r0 + g) * OSTR + d + 1]     = o[nt][1];
        Ob[(r0 + g + 8) * OSTR + d]     = o[nt][2];
        Ob[(r0 + g + 8) * OSTR + d + 1] = o[nt][3];
    }
    __syncthreads();
    float* A = (float*)smem;
    float* B = (float*)(smem + 18432);
    #pragma unroll
    for (int t = 0; t < 4; t++) {
        int idx = tid + t * 256;
        int r = idx >> 4, d4 = (idx & 15) * 4;
        float inv = 1.f / ((ZM[r] + ZM[64 + r]) + 1e-8f * (ZR[r] + ZR[64 + r]));
        float4 a = *(float4*)&A[r * OSTR + d4];
        float4 b = *(float4*)&B[r * OSTR + d4];
        float4 ov = make_float4((a.x + b.x) * inv, (a.y + b.y) * inv,
                                (a.z + b.z) * inv, (a.w + b.w) * inv);
        *(float4*)&out[((size_t)bh * 1024 + m0 + r) * 64 + d4] = ov;
    }
}

extern "C" void kernel_launch(void* const* d_in, const int* in_sizes, int n_in,
                              void* d_out, int out_size)
{
    (void)in_sizes; (void)n_in; (void)out_size;
    const float* q  = (const float*)d_in[0];
    const float* k  = (const float*)d_in[1];
    const float* v  = (const float*)d_in[2];
    const float* pe = (const float*)d_in[3];
    const float* cv = (const float*)d_in[4];

    cvt_pre<<<20544, 256>>>(q, k, v, pe);

    cudaFuncSetAttribute(seqattn_mma, cudaFuncAttributeMaxDynamicSharedMemorySize, SMEM_TOTAL);
    dim3 grid(16, 64);
    seqattn_mma<<<grid, 256, SMEM_TOTAL>>>(cv, (float*)d_out);
}